// round 1
// baseline (speedup 1.0000x reference)
#include <cuda_runtime.h>
#include <cuda_bf16.h>

#define KEPS 0.001f
#define BH   64          // B*H = 4*16
#define SLEN 4096
#define DDIM 64
#define SPLITS 8
#define SCHUNK (SLEN / SPLITS)   // 512

// Scratch (allocation-free rule: __device__ globals)
__device__ float g_pkv[SPLITS * BH * DDIM * DDIM];  // partial kv per split
__device__ float g_pks[SPLITS * BH * DDIM];         // partial ksum per split
__device__ float g_kv[BH * DDIM * DDIM];
__device__ float g_ksum[BH * DDIM];

// ---------------------------------------------------------------------------
// Kernel 1: partial kv[d,e] and ksum[d] over an S-chunk.
// grid = (BH, SPLITS), block = 256.
// Thread t owns (d = t&63, e-range = (t>>6)*16 .. +15) -> 16 accumulators.
// ---------------------------------------------------------------------------
__global__ __launch_bounds__(256) void k_phase1(
    const float* __restrict__ key,
    const float* __restrict__ value,
    const float* __restrict__ mask)
{
    const int bh    = blockIdx.x;
    const int split = blockIdx.y;
    const int b     = bh >> 4;
    const int t     = threadIdx.x;
    const int d     = t & 63;
    const int eg    = t >> 6;          // 0..3
    const int s0    = split * SCHUNK;

    __shared__ float sk[8][64];
    __shared__ float sv[8][64];

    float acc[16];
#pragma unroll
    for (int i = 0; i < 16; i++) acc[i] = 0.0f;
    float ks = 0.0f;

    const float* kp = key   + (size_t)bh * SLEN * DDIM;
    const float* vp = value + (size_t)bh * SLEN * DDIM;
    const float* mp = mask  + (size_t)b * SLEN;

    const int lidx = t & 127;
    const int lr   = lidx >> 4;          // row 0..7
    const int lc   = (lidx & 15) * 4;    // col 0..60

    for (int s = s0; s < s0 + SCHUNK; s += 8) {
        __syncthreads();
        if (t < 128) {
            float4 kk = *(const float4*)(kp + (size_t)(s + lr) * DDIM + lc);
            float  m  = mp[s + lr];
            sk[lr][lc + 0] = (fmaxf(kk.x, 0.0f) + KEPS) * m;
            sk[lr][lc + 1] = (fmaxf(kk.y, 0.0f) + KEPS) * m;
            sk[lr][lc + 2] = (fmaxf(kk.z, 0.0f) + KEPS) * m;
            sk[lr][lc + 3] = (fmaxf(kk.w, 0.0f) + KEPS) * m;
        } else {
            float4 vv = *(const float4*)(vp + (size_t)(s + lr) * DDIM + lc);
            *(float4*)&sv[lr][lc] = vv;
        }
        __syncthreads();

#pragma unroll
        for (int r = 0; r < 8; r++) {
            float kd = sk[r][d];
            ks += kd;                                  // only eg==0's value is used
            float4 v0 = *(const float4*)&sv[r][eg * 16 + 0];
            float4 v1 = *(const float4*)&sv[r][eg * 16 + 4];
            float4 v2 = *(const float4*)&sv[r][eg * 16 + 8];
            float4 v3 = *(const float4*)&sv[r][eg * 16 + 12];
            acc[0]  += kd * v0.x;  acc[1]  += kd * v0.y;
            acc[2]  += kd * v0.z;  acc[3]  += kd * v0.w;
            acc[4]  += kd * v1.x;  acc[5]  += kd * v1.y;
            acc[6]  += kd * v1.z;  acc[7]  += kd * v1.w;
            acc[8]  += kd * v2.x;  acc[9]  += kd * v2.y;
            acc[10] += kd * v2.z;  acc[11] += kd * v2.w;
            acc[12] += kd * v3.x;  acc[13] += kd * v3.y;
            acc[14] += kd * v3.z;  acc[15] += kd * v3.w;
        }
    }

    float* outp = g_pkv + ((size_t)(split * BH + bh)) * DDIM * DDIM + d * DDIM + eg * 16;
#pragma unroll
    for (int i = 0; i < 4; i++) {
        *(float4*)(outp + i * 4) = make_float4(acc[i*4+0], acc[i*4+1], acc[i*4+2], acc[i*4+3]);
    }
    if (eg == 0) g_pks[(split * BH + bh) * DDIM + d] = ks;
}

// ---------------------------------------------------------------------------
// Kernel 2: reduce partials over splits. grid = BH, block = 256.
// ---------------------------------------------------------------------------
__global__ __launch_bounds__(256) void k_reduce()
{
    const int bh = blockIdx.x;
    const int t  = threadIdx.x;

#pragma unroll
    for (int j = 0; j < 16; j++) {
        int idx = t + j * 256;           // 0..4095
        float s = 0.0f;
#pragma unroll
        for (int sp = 0; sp < SPLITS; sp++)
            s += g_pkv[((size_t)(sp * BH + bh)) * DDIM * DDIM + idx];
        g_kv[(size_t)bh * DDIM * DDIM + idx] = s;
    }
    if (t < DDIM) {
        float s = 0.0f;
#pragma unroll
        for (int sp = 0; sp < SPLITS; sp++)
            s += g_pks[(sp * BH + bh) * DDIM + t];
        g_ksum[bh * DDIM + t] = s;
    }
}

// ---------------------------------------------------------------------------
// Kernel 3: out[s,e] = (q . kv[:,e]) / (q . ksum), 64 s-rows per block.
// grid = (chunks=64, BH), block = 256 as 16x16, 4x4 register tile per thread.
// ---------------------------------------------------------------------------
__global__ __launch_bounds__(256) void k_phase2(
    const float* __restrict__ query,
    float* __restrict__ out)
{
    const int chunk = blockIdx.x;        // 0..63
    const int bh    = blockIdx.y;
    const int t     = threadIdx.x;
    const int s0    = chunk * 64;

    __shared__ float skv[64][64];        // kv[d][e]
    __shared__ float sqt[64][68];        // qT[d][s_local], padded
    __shared__ float sks[64];

    const float* qbase = query + (size_t)bh * SLEN * DDIM;
    const float* kvbase = g_kv + (size_t)bh * DDIM * DDIM;

    // load kv: 1024 float4, 4 per thread
#pragma unroll
    for (int j = 0; j < 4; j++) {
        int lin = t + j * 256;           // float4 index 0..1023
        *(float4*)&skv[0][lin * 4] = *(const float4*)(kvbase + lin * 4);
    }
    // load q chunk transposed
#pragma unroll
    for (int j = 0; j < 4; j++) {
        int lin = t + j * 256;           // 0..1023
        int r   = lin >> 4;              // s-local 0..63
        int c   = (lin & 15) * 4;        // d 0..60
        float4 qv = *(const float4*)(qbase + (size_t)(s0 + r) * DDIM + c);
        sqt[c + 0][r] = fmaxf(qv.x, 0.0f) + KEPS;
        sqt[c + 1][r] = fmaxf(qv.y, 0.0f) + KEPS;
        sqt[c + 2][r] = fmaxf(qv.z, 0.0f) + KEPS;
        sqt[c + 3][r] = fmaxf(qv.w, 0.0f) + KEPS;
    }
    if (t < 64) sks[t] = g_ksum[bh * DDIM + t];
    __syncthreads();

    const int tx = t & 15;
    const int ty = t >> 4;
    const int r0 = ty * 4;
    const int c0 = tx * 4;

    float acc[4][4];
    float den[4];
#pragma unroll
    for (int i = 0; i < 4; i++) {
        den[i] = 0.0f;
#pragma unroll
        for (int j = 0; j < 4; j++) acc[i][j] = 0.0f;
    }

#pragma unroll 16
    for (int d = 0; d < 64; d++) {
        float4 qv = *(const float4*)&sqt[d][r0];
        float4 kv4 = *(const float4*)&skv[d][c0];
        float  ksd = sks[d];
        den[0] += qv.x * ksd;
        den[1] += qv.y * ksd;
        den[2] += qv.z * ksd;
        den[3] += qv.w * ksd;
        acc[0][0] += qv.x * kv4.x;  acc[0][1] += qv.x * kv4.y;
        acc[0][2] += qv.x * kv4.z;  acc[0][3] += qv.x * kv4.w;
        acc[1][0] += qv.y * kv4.x;  acc[1][1] += qv.y * kv4.y;
        acc[1][2] += qv.y * kv4.z;  acc[1][3] += qv.y * kv4.w;
        acc[2][0] += qv.z * kv4.x;  acc[2][1] += qv.z * kv4.y;
        acc[2][2] += qv.z * kv4.z;  acc[2][3] += qv.z * kv4.w;
        acc[3][0] += qv.w * kv4.x;  acc[3][1] += qv.w * kv4.y;
        acc[3][2] += qv.w * kv4.z;  acc[3][3] += qv.w * kv4.w;
    }

#pragma unroll
    for (int i = 0; i < 4; i++) {
        float inv = 1.0f / den[i];
        float4 o = make_float4(acc[i][0] * inv, acc[i][1] * inv,
                               acc[i][2] * inv, acc[i][3] * inv);
        *(float4*)(out + (size_t)(bh * SLEN + s0 + r0 + i) * DDIM + c0) = o;
    }
}

// ---------------------------------------------------------------------------
extern "C" void kernel_launch(void* const* d_in, const int* in_sizes, int n_in,
                              void* d_out, int out_size)
{
    const float* query = (const float*)d_in[0];
    const float* key   = (const float*)d_in[1];
    const float* value = (const float*)d_in[2];
    const float* mask  = (const float*)d_in[3];
    float* out = (float*)d_out;

    k_phase1<<<dim3(BH, SPLITS), 256>>>(key, value, mask);
    k_reduce<<<BH, 256>>>();
    k_phase2<<<dim3(SLEN / 64, BH), 256>>>(query, out);
}

// round 2
// speedup vs baseline: 1.0468x; 1.0468x over previous
#include <cuda_runtime.h>
#include <cuda_bf16.h>

#define KEPS 0.001f
#define BH     64         // B*H = 4*16
#define SLEN   4096
#define DDIM   64
#define SPLITS 8
#define SCHUNK (SLEN / SPLITS)   // 512
#define P1ROWS 16

// Scratch (allocation-free rule: __device__ globals)
__device__ float g_pkv[SPLITS * BH * DDIM * DDIM];  // 8 MB partial kv
__device__ float g_pks[SPLITS * BH * DDIM];
__device__ float g_kv[BH * DDIM * DDIM];
__device__ float g_ksum[BH * DDIM];

// ---------------------------------------------------------------------------
// Phase 1: partial kv[d,e] and ksum[d] over an S-chunk.
// grid = (BH, SPLITS), block = 128.
// Thread: lane = t&31 owns d-rows {lane, lane+32}; warp eg = t>>5 owns 16 e.
// 32 accumulators/thread; per s-row: 2 scalar LDS + 4 bcast LDS.128 + 34 fma.
// ---------------------------------------------------------------------------
__global__ __launch_bounds__(128) void k_phase1(
    const float* __restrict__ key,
    const float* __restrict__ value,
    const float* __restrict__ mask)
{
    const int bh    = blockIdx.x;
    const int split = blockIdx.y;
    const int b     = bh >> 4;
    const int t     = threadIdx.x;
    const int lane  = t & 31;
    const int eg    = t >> 5;            // 0..3 -> e-range eg*16..+15

    __shared__ float sk[P1ROWS][DDIM];
    __shared__ float sv[P1ROWS][DDIM];

    float acc0[16], acc1[16];
#pragma unroll
    for (int i = 0; i < 16; i++) { acc0[i] = 0.0f; acc1[i] = 0.0f; }
    float ks0 = 0.0f, ks1 = 0.0f;

    const float* kp = key   + (size_t)bh * SLEN * DDIM;
    const float* vp = value + (size_t)bh * SLEN * DDIM;
    const float* mp = mask  + (size_t)b * SLEN;

    // load mapping: 256 float4 per array per step, 2 per thread
    const int lr = t >> 4;               // row 0..7  (second row = lr+8)
    const int lc = (t & 15) * 4;         // col 0..60

    const int s0 = split * SCHUNK;

    for (int step = 0; step < SCHUNK / P1ROWS; step++) {
        const int s = s0 + step * P1ROWS;

        // stage global -> regs
        float4 ka = *(const float4*)(kp + (size_t)(s + lr) * DDIM + lc);
        float4 kb = *(const float4*)(kp + (size_t)(s + lr + 8) * DDIM + lc);
        float4 va = *(const float4*)(vp + (size_t)(s + lr) * DDIM + lc);
        float4 vb = *(const float4*)(vp + (size_t)(s + lr + 8) * DDIM + lc);
        float  ma = mp[s + lr];
        float  mb = mp[s + lr + 8];

        __syncthreads();
        sk[lr][lc + 0] = (fmaxf(ka.x, 0.0f) + KEPS) * ma;
        sk[lr][lc + 1] = (fmaxf(ka.y, 0.0f) + KEPS) * ma;
        sk[lr][lc + 2] = (fmaxf(ka.z, 0.0f) + KEPS) * ma;
        sk[lr][lc + 3] = (fmaxf(ka.w, 0.0f) + KEPS) * ma;
        sk[lr + 8][lc + 0] = (fmaxf(kb.x, 0.0f) + KEPS) * mb;
        sk[lr + 8][lc + 1] = (fmaxf(kb.y, 0.0f) + KEPS) * mb;
        sk[lr + 8][lc + 2] = (fmaxf(kb.z, 0.0f) + KEPS) * mb;
        sk[lr + 8][lc + 3] = (fmaxf(kb.w, 0.0f) + KEPS) * mb;
        *(float4*)&sv[lr][lc]     = va;
        *(float4*)&sv[lr + 8][lc] = vb;
        __syncthreads();

#pragma unroll
        for (int r = 0; r < P1ROWS; r++) {
            float kd0 = sk[r][lane];
            float kd1 = sk[r][lane + 32];
            ks0 += kd0;
            ks1 += kd1;
            const float4* vr = (const float4*)&sv[r][eg * 16];
            float4 v0 = vr[0], v1 = vr[1], v2 = vr[2], v3 = vr[3];
            acc0[0]  += kd0 * v0.x;  acc0[1]  += kd0 * v0.y;
            acc0[2]  += kd0 * v0.z;  acc0[3]  += kd0 * v0.w;
            acc0[4]  += kd0 * v1.x;  acc0[5]  += kd0 * v1.y;
            acc0[6]  += kd0 * v1.z;  acc0[7]  += kd0 * v1.w;
            acc0[8]  += kd0 * v2.x;  acc0[9]  += kd0 * v2.y;
            acc0[10] += kd0 * v2.z;  acc0[11] += kd0 * v2.w;
            acc0[12] += kd0 * v3.x;  acc0[13] += kd0 * v3.y;
            acc0[14] += kd0 * v3.z;  acc0[15] += kd0 * v3.w;
            acc1[0]  += kd1 * v0.x;  acc1[1]  += kd1 * v0.y;
            acc1[2]  += kd1 * v0.z;  acc1[3]  += kd1 * v0.w;
            acc1[4]  += kd1 * v1.x;  acc1[5]  += kd1 * v1.y;
            acc1[6]  += kd1 * v1.z;  acc1[7]  += kd1 * v1.w;
            acc1[8]  += kd1 * v2.x;  acc1[9]  += kd1 * v2.y;
            acc1[10] += kd1 * v2.z;  acc1[11] += kd1 * v2.w;
            acc1[12] += kd1 * v3.x;  acc1[13] += kd1 * v3.y;
            acc1[14] += kd1 * v3.z;  acc1[15] += kd1 * v3.w;
        }
    }

    float* p0 = g_pkv + ((size_t)(split * BH + bh)) * DDIM * DDIM + lane * DDIM + eg * 16;
    float* p1 = p0 + 32 * DDIM;
#pragma unroll
    for (int i = 0; i < 4; i++) {
        *(float4*)(p0 + i * 4) = make_float4(acc0[i*4+0], acc0[i*4+1], acc0[i*4+2], acc0[i*4+3]);
        *(float4*)(p1 + i * 4) = make_float4(acc1[i*4+0], acc1[i*4+1], acc1[i*4+2], acc1[i*4+3]);
    }
    if (eg == 0) {
        g_pks[(split * BH + bh) * DDIM + lane]      = ks0;
        g_pks[(split * BH + bh) * DDIM + lane + 32] = ks1;
    }
}

// ---------------------------------------------------------------------------
// Reduce partials over splits. grid = 272, block = 256.
// Blocks [0,256): kv as float4 (65536 float4). Blocks [256,272): ksum (4096).
// ---------------------------------------------------------------------------
__global__ __launch_bounds__(256) void k_reduce()
{
    const int bidx = blockIdx.x;
    const int t    = threadIdx.x;
    if (bidx < 256) {
        int fi = bidx * 256 + t;         // float4 index 0..65535
        const float4* src = (const float4*)g_pkv;
        float4 s = make_float4(0.f, 0.f, 0.f, 0.f);
#pragma unroll
        for (int sp = 0; sp < SPLITS; sp++) {
            float4 v = src[(size_t)sp * 65536 + fi];
            s.x += v.x; s.y += v.y; s.z += v.z; s.w += v.w;
        }
        ((float4*)g_kv)[fi] = s;
    } else {
        int i = (bidx - 256) * 256 + t;  // 0..4095
        float s = 0.0f;
#pragma unroll
        for (int sp = 0; sp < SPLITS; sp++) s += g_pks[sp * BH * DDIM + i];
        g_ksum[i] = s;
    }
}

// ---------------------------------------------------------------------------
// Phase 2: out[s,e] = (q . kv[:,e]) / (q . ksum)
// grid = (64, BH), block = 128; 64s x 64e tile; per-thread 4s x 8e.
// ---------------------------------------------------------------------------
__global__ __launch_bounds__(128) void k_phase2(
    const float* __restrict__ query,
    float* __restrict__ out)
{
    const int chunk = blockIdx.x;        // 0..63
    const int bh    = blockIdx.y;
    const int t     = threadIdx.x;
    const int s0    = chunk * 64;

    __shared__ float skv[DDIM][DDIM];    // kv[d][e]  (16 KB)
    __shared__ float sqt[DDIM][68];      // qT[d][s_local] padded (17.4 KB)
    __shared__ float sks[DDIM];

    const float* qbase  = query + (size_t)bh * SLEN * DDIM;
    const float* kvbase = g_kv  + (size_t)bh * DDIM * DDIM;

#pragma unroll
    for (int j = 0; j < 8; j++) {
        int lin = t + j * 128;           // float4 idx 0..1023
        *(float4*)&skv[0][lin * 4] = *(const float4*)(kvbase + lin * 4);
    }
#pragma unroll
    for (int j = 0; j < 8; j++) {
        int lin = t + j * 128;           // 0..1023
        int r   = lin >> 4;              // s-local 0..63
        int c   = (lin & 15) * 4;        // d 0..60
        float4 qv = *(const float4*)(qbase + (size_t)(s0 + r) * DDIM + c);
        sqt[c + 0][r] = fmaxf(qv.x, 0.0f) + KEPS;
        sqt[c + 1][r] = fmaxf(qv.y, 0.0f) + KEPS;
        sqt[c + 2][r] = fmaxf(qv.z, 0.0f) + KEPS;
        sqt[c + 3][r] = fmaxf(qv.w, 0.0f) + KEPS;
    }
    if (t < DDIM) sks[t] = g_ksum[bh * DDIM + t];
    __syncthreads();

    const int tx = t & 7;                // e-group: 8 cols
    const int ty = t >> 3;               // s-group: 4 rows
    const int c0 = tx * 8;
    const int r0 = ty * 4;

    float acc[4][8];
    float den[4];
#pragma unroll
    for (int i = 0; i < 4; i++) {
        den[i] = 0.0f;
#pragma unroll
        for (int j = 0; j < 8; j++) acc[i][j] = 0.0f;
    }

#pragma unroll 16
    for (int d = 0; d < DDIM; d++) {
        float4 qv = *(const float4*)&sqt[d][r0];
        float4 ca = *(const float4*)&skv[d][c0];
        float4 cb = *(const float4*)&skv[d][c0 + 4];
        float  kd = sks[d];
        den[0] += qv.x * kd;  den[1] += qv.y * kd;
        den[2] += qv.z * kd;  den[3] += qv.w * kd;
        acc[0][0] += qv.x * ca.x;  acc[0][1] += qv.x * ca.y;
        acc[0][2] += qv.x * ca.z;  acc[0][3] += qv.x * ca.w;
        acc[0][4] += qv.x * cb.x;  acc[0][5] += qv.x * cb.y;
        acc[0][6] += qv.x * cb.z;  acc[0][7] += qv.x * cb.w;
        acc[1][0] += qv.y * ca.x;  acc[1][1] += qv.y * ca.y;
        acc[1][2] += qv.y * ca.z;  acc[1][3] += qv.y * ca.w;
        acc[1][4] += qv.y * cb.x;  acc[1][5] += qv.y * cb.y;
        acc[1][6] += qv.y * cb.z;  acc[1][7] += qv.y * cb.w;
        acc[2][0] += qv.z * ca.x;  acc[2][1] += qv.z * ca.y;
        acc[2][2] += qv.z * ca.z;  acc[2][3] += qv.z * ca.w;
        acc[2][4] += qv.z * cb.x;  acc[2][5] += qv.z * cb.y;
        acc[2][6] += qv.z * cb.z;  acc[2][7] += qv.z * cb.w;
        acc[3][0] += qv.w * ca.x;  acc[3][1] += qv.w * ca.y;
        acc[3][2] += qv.w * ca.z;  acc[3][3] += qv.w * ca.w;
        acc[3][4] += qv.w * cb.x;  acc[3][5] += qv.w * cb.y;
        acc[3][6] += qv.w * cb.z;  acc[3][7] += qv.w * cb.w;
    }

#pragma unroll
    for (int i = 0; i < 4; i++) {
        float inv = 1.0f / den[i];
        float* op = out + (size_t)(bh * SLEN + s0 + r0 + i) * DDIM + c0;
        *(float4*)op = make_float4(acc[i][0] * inv, acc[i][1] * inv,
                                   acc[i][2] * inv, acc[i][3] * inv);
        *(float4*)(op + 4) = make_float4(acc[i][4] * inv, acc[i][5] * inv,
                                         acc[i][6] * inv, acc[i][7] * inv);
    }
}

// ---------------------------------------------------------------------------
extern "C" void kernel_launch(void* const* d_in, const int* in_sizes, int n_in,
                              void* d_out, int out_size)
{
    const float* query = (const float*)d_in[0];
    const float* key   = (const float*)d_in[1];
    const float* value = (const float*)d_in[2];
    const float* mask  = (const float*)d_in[3];
    float* out = (float*)d_out;

    k_phase1<<<dim3(BH, SPLITS), 128>>>(key, value, mask);
    k_reduce<<<272, 256>>>();
    k_phase2<<<dim3(SLEN / 64, BH), 128>>>(query, out);
}

// round 4
// speedup vs baseline: 1.7382x; 1.6605x over previous
#include <cuda_runtime.h>
#include <cuda_bf16.h>
#include <cstdint>

#define KEPS   0.001f
#define BH     64
#define SLEN   4096
#define DDIM   64
#define SPLITS 16
#define SCHUNK (SLEN / SPLITS)     // 256
#define NROWS  72                  // B rows: 64 kv-cols + ksum + 7 pad

// ---------------- scratch (__device__ globals; allocation-free rule) -------
__device__ float         g_pkv[SPLITS * BH * NROWS * DDIM];   // ~18.9 MB
__device__ __nv_bfloat16 g_bhi[BH * NROWS * DDIM];
__device__ __nv_bfloat16 g_blo[BH * NROWS * DDIM];

// ---------------- helpers ---------------------------------------------------
__device__ __forceinline__ uint32_t s2u(const void* p) {
    uint32_t a;
    asm("{ .reg .u64 t; cvta.to.shared.u64 t, %1; cvt.u32.u64 %0, t; }"
        : "=r"(a) : "l"(p));
    return a;
}

__device__ __forceinline__ void mma16816(float* c, const uint32_t* a, const uint32_t* b) {
    asm volatile(
        "mma.sync.aligned.m16n8k16.row.col.f32.bf16.bf16.f32 "
        "{%0,%1,%2,%3}, {%4,%5,%6,%7}, {%8,%9}, {%0,%1,%2,%3};"
        : "+f"(c[0]), "+f"(c[1]), "+f"(c[2]), "+f"(c[3])
        : "r"(a[0]), "r"(a[1]), "r"(a[2]), "r"(a[3]), "r"(b[0]), "r"(b[1]));
}
__device__ __forceinline__ void ldsm_x4(uint32_t* r, uint32_t addr) {
    asm volatile("ldmatrix.sync.aligned.m8n8.x4.shared.b16 {%0,%1,%2,%3}, [%4];"
        : "=r"(r[0]), "=r"(r[1]), "=r"(r[2]), "=r"(r[3]) : "r"(addr));
}
__device__ __forceinline__ void ldsm_x4_t(uint32_t* r, uint32_t addr) {
    asm volatile("ldmatrix.sync.aligned.m8n8.x4.trans.shared.b16 {%0,%1,%2,%3}, [%4];"
        : "=r"(r[0]), "=r"(r[1]), "=r"(r[2]), "=r"(r[3]) : "r"(addr));
}
__device__ __forceinline__ void ldsm_x2(uint32_t* r, uint32_t addr) {
    asm volatile("ldmatrix.sync.aligned.m8n8.x2.shared.b16 {%0,%1}, [%2];"
        : "=r"(r[0]), "=r"(r[1]) : "r"(addr));
}
__device__ __forceinline__ void ldsm_x2_t(uint32_t* r, uint32_t addr) {
    asm volatile("ldmatrix.sync.aligned.m8n8.x2.trans.shared.b16 {%0,%1}, [%2];"
        : "=r"(r[0]), "=r"(r[1]) : "r"(addr));
}
__device__ __forceinline__ void bfsplit(float x, __nv_bfloat16& h, __nv_bfloat16& l) {
    h = __float2bfloat16(x);
    l = __float2bfloat16(x - __bfloat162float(h));
}

// ---------------------------------------------------------------------------
// Phase 1 (HMMA): partial M[e,d] = sum_s v_ext[s,e] * k_eff[s,d] over S-chunk.
//   v_ext: cols 0-63 = v, col 64 = 1 (-> ksum), 65-79 = 0.
// grid = (BH, SPLITS), block = 128 (4 warps; warp owns d-range warp*16..+15).
// ---------------------------------------------------------------------------
__global__ __launch_bounds__(128) void k_phase1(
    const float* __restrict__ key,
    const float* __restrict__ value,
    const float* __restrict__ mask)
{
    __shared__ __nv_bfloat16 skh[64][72], skl[64][72];   // k_eff hi/lo
    __shared__ __nv_bfloat16 svh[64][88], svl[64][88];   // v_ext hi/lo

    const int bh    = blockIdx.x;
    const int split = blockIdx.y;
    const int b     = bh >> 4;
    const int t     = threadIdx.x;
    const int warp  = t >> 5;
    const int lane  = t & 31;

    // init v pad cols 64..79 (constant across buffers; cols 0-63 rewritten each buf)
    for (int i = t; i < 64 * 24; i += 128) {
        int row = i / 24, col = 64 + (i % 24);
        svh[row][col] = __float2bfloat16(col == 64 ? 1.0f : 0.0f);
        svl[row][col] = __float2bfloat16(0.0f);
    }

    float acc[5][2][4];
#pragma unroll
    for (int i = 0; i < 5; i++)
#pragma unroll
        for (int j = 0; j < 2; j++)
#pragma unroll
            for (int q = 0; q < 4; q++) acc[i][j][q] = 0.0f;

    const float* kp = key   + (size_t)bh * SLEN * DDIM;
    const float* vp = value + (size_t)bh * SLEN * DDIM;
    const float* mp = mask  + (size_t)b * SLEN;
    const int s0 = split * SCHUNK;

    const uint32_t a_kh = s2u(&skh[0][0]), a_kl = s2u(&skl[0][0]);
    const uint32_t a_vh = s2u(&svh[0][0]), a_vl = s2u(&svl[0][0]);

    const int grp = lane >> 3, jj = lane & 7, l15 = lane & 15;

    for (int buf = 0; buf < SCHUNK / 64; buf++) {
        const int sg = s0 + buf * 64;
        __syncthreads();
#pragma unroll
        for (int i = 0; i < 8; i++) {
            int lin = t + i * 128;             // 0..1023
            int row = lin >> 4, c4 = (lin & 15) * 4;
            float4 kk = *(const float4*)(kp + (size_t)(sg + row) * DDIM + c4);
            float  m  = mp[sg + row];
            float x0 = (fmaxf(kk.x, 0.0f) + KEPS) * m;
            float x1 = (fmaxf(kk.y, 0.0f) + KEPS) * m;
            float x2 = (fmaxf(kk.z, 0.0f) + KEPS) * m;
            float x3 = (fmaxf(kk.w, 0.0f) + KEPS) * m;
            __nv_bfloat16 h0,h1,h2,h3,l0,l1,l2,l3;
            bfsplit(x0,h0,l0); bfsplit(x1,h1,l1); bfsplit(x2,h2,l2); bfsplit(x3,h3,l3);
            __nv_bfloat162 p;
            p.x=h0; p.y=h1; *(__nv_bfloat162*)&skh[row][c4]   = p;
            p.x=h2; p.y=h3; *(__nv_bfloat162*)&skh[row][c4+2] = p;
            p.x=l0; p.y=l1; *(__nv_bfloat162*)&skl[row][c4]   = p;
            p.x=l2; p.y=l3; *(__nv_bfloat162*)&skl[row][c4+2] = p;

            float4 vv = *(const float4*)(vp + (size_t)(sg + row) * DDIM + c4);
            bfsplit(vv.x,h0,l0); bfsplit(vv.y,h1,l1);
            bfsplit(vv.z,h2,l2); bfsplit(vv.w,h3,l3);
            p.x=h0; p.y=h1; *(__nv_bfloat162*)&svh[row][c4]   = p;
            p.x=h2; p.y=h3; *(__nv_bfloat162*)&svh[row][c4+2] = p;
            p.x=l0; p.y=l1; *(__nv_bfloat162*)&svl[row][c4]   = p;
            p.x=l2; p.y=l3; *(__nv_bfloat162*)&svl[row][c4+2] = p;
        }
        __syncthreads();

#pragma unroll
        for (int ks = 0; ks < 64; ks += 16) {
            // B frags from k smem ([s][d], trans): pair along s
            uint32_t Bh[2][2], Bl[2][2];
#pragma unroll
            for (int nt = 0; nt < 2; nt++) {
                int d0 = warp * 16 + nt * 8;
                ldsm_x2_t(Bh[nt], a_kh + (uint32_t)(((ks + l15) * 72 + d0) * 2));
                ldsm_x2_t(Bl[nt], a_kl + (uint32_t)(((ks + l15) * 72 + d0) * 2));
            }
            const int vrow = ks + jj + ((grp >> 1) << 3);
#pragma unroll
            for (int mt = 0; mt < 5; mt++) {
                int e0 = mt * 16 + ((grp & 1) << 3);
                uint32_t Ah[4], Al[4];
                ldsm_x4_t(Ah, a_vh + (uint32_t)((vrow * 88 + e0) * 2));
                ldsm_x4_t(Al, a_vl + (uint32_t)((vrow * 88 + e0) * 2));
#pragma unroll
                for (int nt = 0; nt < 2; nt++) {
                    mma16816(acc[mt][nt], Ah, Bh[nt]);
                    mma16816(acc[mt][nt], Ah, Bl[nt]);
                    mma16816(acc[mt][nt], Al, Bh[nt]);
                }
            }
        }
    }

    // store fp32 partials: layout [e up to 72][d 64]
    float* pkv = g_pkv + ((size_t)(split * BH + bh)) * NROWS * DDIM;
    const int r = lane >> 2, c2 = (lane & 3) * 2;
#pragma unroll
    for (int mt = 0; mt < 5; mt++)
#pragma unroll
        for (int nt = 0; nt < 2; nt++) {
            int e = mt * 16 + r;
            int d = warp * 16 + nt * 8 + c2;
            *(float2*)(pkv + e * DDIM + d) = make_float2(acc[mt][nt][0], acc[mt][nt][1]);
            if (mt < 4)
                *(float2*)(pkv + (e + 8) * DDIM + d) = make_float2(acc[mt][nt][2], acc[mt][nt][3]);
        }
}

// ---------------------------------------------------------------------------
// Reduce over splits -> bf16 hi/lo B tiles [72][64]. grid = BH, block = 256.
// ---------------------------------------------------------------------------
__global__ __launch_bounds__(256) void k_reduce()
{
    const int bh = blockIdx.x;
    const int t  = threadIdx.x;
#pragma unroll
    for (int j = 0; j < 18; j++) {
        int idx = t + j * 256;               // 0..4607
        float s = 0.0f;
#pragma unroll
        for (int sp = 0; sp < SPLITS; sp++)
            s += g_pkv[((size_t)(sp * BH + bh)) * NROWS * DDIM + idx];
        __nv_bfloat16 h, l;
        bfsplit(s, h, l);
        g_bhi[(size_t)bh * NROWS * DDIM + idx] = h;
        g_blo[(size_t)bh * NROWS * DDIM + idx] = l;
    }
}

// ---------------------------------------------------------------------------
// Phase 2 (HMMA): D[128s x 72n] = Q_eff[128x64] . B[72x64]^T ; n=64 col = denom.
// grid = (SLEN/128, BH), block = 128. dynamic smem 57600 B.
// ---------------------------------------------------------------------------
#define OFF_QHI 0
#define OFF_QLO 18432
#define OFF_BHI 36864
#define OFF_BLO 47232
#define P2_SMEM 57600

__global__ __launch_bounds__(128) void k_phase2(
    const float* __restrict__ query,
    float* __restrict__ out)
{
    extern __shared__ char smem[];
    const uint32_t sb = s2u(smem);
    const int t    = threadIdx.x;
    const int warp = t >> 5;
    const int lane = t & 31;
    const int s0   = blockIdx.x * 128;
    const int bh   = blockIdx.y;

    // ---- B tiles (bf16 hi/lo, [72 n][64 k] -> smem stride 72) ----
    {
        const uint4* gh = (const uint4*)(g_bhi + (size_t)bh * NROWS * DDIM);
        const uint4* gl = (const uint4*)(g_blo + (size_t)bh * NROWS * DDIM);
#pragma unroll
        for (int i = 0; i < 5; i++) {
            int lin = t + i * 128;
            if (lin < 576) {
                int row = lin >> 3, col = (lin & 7) * 8;
                *(uint4*)(smem + OFF_BHI + (row * 72 + col) * 2) = gh[lin];
                *(uint4*)(smem + OFF_BLO + (row * 72 + col) * 2) = gl[lin];
            }
        }
    }
    // ---- Q tile: 128x64 fp32 -> relu+eps -> bf16 hi/lo (stride 72) ----
    {
        const float* qp = query + ((size_t)bh * SLEN + s0) * DDIM;
#pragma unroll
        for (int i = 0; i < 16; i++) {
            int lin = t + i * 128;            // 0..2047
            int row = lin >> 4, c4 = (lin & 15) * 4;
            float4 qv = *(const float4*)(qp + (size_t)row * DDIM + c4);
            float x0 = fmaxf(qv.x, 0.0f) + KEPS;
            float x1 = fmaxf(qv.y, 0.0f) + KEPS;
            float x2 = fmaxf(qv.z, 0.0f) + KEPS;
            float x3 = fmaxf(qv.w, 0.0f) + KEPS;
            __nv_bfloat16 h0,h1,h2,h3,l0,l1,l2,l3;
            bfsplit(x0,h0,l0); bfsplit(x1,h1,l1); bfsplit(x2,h2,l2); bfsplit(x3,h3,l3);
            __nv_bfloat162 p;
            char* qh = smem + OFF_QHI + (row * 72 + c4) * 2;
            char* ql = smem + OFF_QLO + (row * 72 + c4) * 2;
            p.x=h0; p.y=h1; *(__nv_bfloat162*)qh = p;
            p.x=h2; p.y=h3; *(__nv_bfloat162*)(qh + 4) = p;
            p.x=l0; p.y=l1; *(__nv_bfloat162*)ql = p;
            p.x=l2; p.y=l3; *(__nv_bfloat162*)(ql + 4) = p;
        }
    }
    __syncthreads();

    float acc[2][9][4];
#pragma unroll
    for (int i = 0; i < 2; i++)
#pragma unroll
        for (int j = 0; j < 9; j++)
#pragma unroll
            for (int q = 0; q < 4; q++) acc[i][j][q] = 0.0f;

    const int grp = lane >> 3, jj = lane & 7, l15 = lane & 15;

#pragma unroll
    for (int k0 = 0; k0 < 64; k0 += 16) {
        uint32_t Bh[9][2], Bl[9][2];
#pragma unroll
        for (int nt = 0; nt < 9; nt++) {
            uint32_t off = (uint32_t)(((nt * 8 + (l15 & 7)) * 72 + k0 + ((l15 >> 3) << 3)) * 2);
            ldsm_x2(Bh[nt], sb + OFF_BHI + off);
            ldsm_x2(Bl[nt], sb + OFF_BLO + off);
        }
#pragma unroll
        for (int mt = 0; mt < 2; mt++) {
            int qrow = warp * 32 + mt * 16 + jj + ((grp & 1) << 3);
            int qcol = k0 + ((grp >> 1) << 3);
            uint32_t Ah[4], Al[4];
            ldsm_x4(Ah, sb + OFF_QHI + (uint32_t)((qrow * 72 + qcol) * 2));
            ldsm_x4(Al, sb + OFF_QLO + (uint32_t)((qrow * 72 + qcol) * 2));
#pragma unroll
            for (int nt = 0; nt < 9; nt++) {
                mma16816(acc[mt][nt], Ah, Bh[nt]);
                mma16816(acc[mt][nt], Ah, Bl[nt]);
                mma16816(acc[mt][nt], Al, Bh[nt]);
            }
        }
    }
    __syncthreads();   // done reading Q smem; reuse as stage (stride 68 floats)

    float* stage = (float*)smem;
    const int r = lane >> 2, c2 = (lane & 3) * 2;
#pragma unroll
    for (int mt = 0; mt < 2; mt++) {
        float dlo = __shfl_sync(0xffffffffu, acc[mt][8][0], lane & 28);
        float dhi = __shfl_sync(0xffffffffu, acc[mt][8][2], lane & 28);
        float ilo = 1.0f / dlo;
        float ihi = 1.0f / dhi;
        int r0 = warp * 32 + mt * 16 + r;
#pragma unroll
        for (int nt = 0; nt < 8; nt++) {
            int c = nt * 8 + c2;
            *(float2*)(stage + r0 * 68 + c) =
                make_float2(acc[mt][nt][0] * ilo, acc[mt][nt][1] * ilo);
            *(float2*)(stage + (r0 + 8) * 68 + c) =
                make_float2(acc[mt][nt][2] * ihi, acc[mt][nt][3] * ihi);
        }
    }
    __syncthreads();

    float* ob = out + ((size_t)bh * SLEN + s0) * DDIM;
#pragma unroll
    for (int i = 0; i < 16; i++) {
        int lin = t + i * 128;
        int row = lin >> 4, c = (lin & 15) * 4;
        *(float4*)(ob + (size_t)row * DDIM + c) = *(const float4*)(stage + row * 68 + c);
    }
}

// ---------------------------------------------------------------------------
extern "C" void kernel_launch(void* const* d_in, const int* in_sizes, int n_in,
                              void* d_out, int out_size)
{
    const float* query = (const float*)d_in[0];
    const float* key   = (const float*)d_in[1];
    const float* value = (const float*)d_in[2];
    const float* mask  = (const float*)d_in[3];
    float* out = (float*)d_out;

    cudaFuncSetAttribute(k_phase2, cudaFuncAttributeMaxDynamicSharedMemorySize, P2_SMEM);

    k_phase1<<<dim3(BH, SPLITS), 128>>>(key, value, mask);
    k_reduce<<<BH, 256>>>();
    k_phase2<<<dim3(SLEN / 128, BH), 128, P2_SMEM>>>(query, out);
}